// round 14
// baseline (speedup 1.0000x reference)
#include <cuda_runtime.h>
#include <cuda_fp16.h>
#include <stdint.h>
#include <math.h>

// Problem constants (fixed shapes)
#define BATCH   2
#define SEQ     2048
#define DMODEL  1024
#define NHEAD   16
#define HDIM    64
#define MTOT    (BATCH*SEQ)   // 4096

#define LOG2E   1.4426950408889634f

// ---------------- scratch (__device__ globals; no allocs allowed) ----------
__device__ __half g_xh[3][MTOT * DMODEL];   // q,k,v input activations (fp16)
__device__ __half g_wh[4][DMODEL * DMODEL]; // WQ,WK,WV,WO (fp16)
__device__ __half g_ph[3][MTOT * DMODEL];   // projected Q,K,V (Q pre-scaled)
__device__ __half g_ch[MTOT * DMODEL];      // ctx (fp16)
__device__ unsigned char g_mzero[BATCH * 16 * 32]; // 1 = 128x64 mask tile all-zero

// ---------------- portable PTX helpers -------------------------------------
__device__ __forceinline__ uint32_t smem_u32(const void* p) {
    uint32_t a;
    asm("{ .reg .u64 t; cvta.to.shared.u64 t, %1; cvt.u32.u64 %0, t; }"
        : "=r"(a) : "l"(p));
    return a;
}
__device__ __forceinline__ void cp_async16(uint32_t dst, const void* src) {
    asm volatile("cp.async.cg.shared.global [%0], [%1], 16;"
                 :: "r"(dst), "l"(src));
}
#define CP_COMMIT()  asm volatile("cp.async.commit_group;" ::: "memory")
#define CP_WAIT(N)   asm volatile("cp.async.wait_group %0;" :: "n"(N) : "memory")

__device__ __forceinline__ void ldsm4(uint32_t* r, uint32_t addr) {
    asm volatile("ldmatrix.sync.aligned.m8n8.x4.shared.b16 {%0,%1,%2,%3}, [%4];"
                 : "=r"(r[0]), "=r"(r[1]), "=r"(r[2]), "=r"(r[3]) : "r"(addr));
}
__device__ __forceinline__ void ldsm4t(uint32_t* r, uint32_t addr) {
    asm volatile("ldmatrix.sync.aligned.m8n8.x4.trans.shared.b16 {%0,%1,%2,%3}, [%4];"
                 : "=r"(r[0]), "=r"(r[1]), "=r"(r[2]), "=r"(r[3]) : "r"(addr));
}
__device__ __forceinline__ void mma16816(float* c, const uint32_t* a,
                                         const uint32_t* b) {
    asm volatile(
        "mma.sync.aligned.m16n8k16.row.col.f32.f16.f16.f32 "
        "{%0,%1,%2,%3}, {%4,%5,%6,%7}, {%8,%9}, {%0,%1,%2,%3};"
        : "+f"(c[0]), "+f"(c[1]), "+f"(c[2]), "+f"(c[3])
        : "r"(a[0]), "r"(a[1]), "r"(a[2]), "r"(a[3]), "r"(b[0]), "r"(b[1]));
}
__device__ __forceinline__ float ex2f(float x) {
    float r;
    asm("ex2.approx.f32 %0, %1;" : "=f"(r) : "f"(x));
    return r;
}
__device__ __forceinline__ uint32_t ex2h2(uint32_t x) {
    uint32_t r;
    asm("ex2.approx.f16x2 %0, %1;" : "=r"(r) : "r"(x));
    return r;
}
__device__ __forceinline__ uint32_t h2_as_u32(__half2 v) {
    return *reinterpret_cast<uint32_t*>(&v);
}
__device__ __forceinline__ __half2 u32_as_h2(uint32_t v) {
    return *reinterpret_cast<__half2*>(&v);
}

// ---------------------------------------------------------------------------
// fp32 -> fp16 conversion (fused: z<3 activations, z>=3 weights)
// ---------------------------------------------------------------------------
__global__ __launch_bounds__(256) void prep(const float* __restrict__ q,
                                            const float* __restrict__ k,
                                            const float* __restrict__ v,
                                            const float* __restrict__ wq,
                                            const float* __restrict__ wk,
                                            const float* __restrict__ wv,
                                            const float* __restrict__ wo) {
    const int z = blockIdx.y;
    const float* srcs[7] = {q, k, v, wq, wk, wv, wo};
    __half* dsts[7] = {g_xh[0], g_xh[1], g_xh[2],
                       g_wh[0], g_wh[1], g_wh[2], g_wh[3]};
    if (z >= 3 && blockIdx.x >= DMODEL * DMODEL / 1024) return;
    const float* s = srcs[z];
    __half* d = dsts[z];
    int i = (blockIdx.x * 256 + threadIdx.x) * 4;
    float4 x = *(const float4*)(s + i);
    *(__half2*)(d + i)     = __floats2half2_rn(x.x, x.y);
    *(__half2*)(d + i + 2) = __floats2half2_rn(x.z, x.w);
}

// ---------------------------------------------------------------------------
// Per-tile mask zero-flag: g_mzero[b][qt][kt] = (128x64 tile entirely 0.0f)
// ---------------------------------------------------------------------------
__global__ __launch_bounds__(256) void mask_flags(const float* __restrict__ mask) {
    const int kt = blockIdx.x, qt = blockIdx.y, b = blockIdx.z;
    const int tid = threadIdx.x;
    const int row = tid >> 2;
    const int c0  = (tid & 3) * 16;
    int nz = 0;
#pragma unroll
    for (int half = 0; half < 2; half++) {
        const float* p = mask + ((size_t)b * SEQ + qt * 128 + half * 64 + row) * SEQ
                         + kt * 64 + c0;
#pragma unroll
        for (int i = 0; i < 4; i++) {
            float4 v = *(const float4*)(p + i * 4);
            nz |= (v.x != 0.0f) | (v.y != 0.0f) | (v.z != 0.0f) | (v.w != 0.0f);
        }
    }
    nz = __syncthreads_or(nz);
    if (tid == 0)
        g_mzero[(b * 16 + qt) * 32 + kt] = (unsigned char)(nz == 0);
}

// ---------------------------------------------------------------------------
// Warp-MMA GEMM (NT): C[128,128]/CTA = A[M,K] * B[N,K]^T + bias, pure fp16.
// 128 threads / 4 warps (2x2), warp tile 64x64.
// 3-stage smem ring -> ONE barrier per k-chunk.
// OUT: 0 = fp32 + bias; 2 = f16 * oscale.
// ---------------------------------------------------------------------------
#define BUFB     32768
#define MMA_SMEM (3 * BUFB)   // 98304

template<int OUT>
__device__ __forceinline__ void mma_gemm_body(
    const __half* __restrict__ Ah,
    const __half* __restrict__ Bh,
    const float* __restrict__ bias,
    float* __restrict__ Cf,
    __half* __restrict__ Chi,
    float oscale)
{
    extern __shared__ char sm[];
    const uint32_t sb = smem_u32(sm);
    const int tid  = threadIdx.x;
    const int lane = tid & 31;
    const int warp = tid >> 5;            // 0..3
    const int row0 = blockIdx.y * 128;
    const int col0 = blockIdx.x * 128;
    const int m0w  = (warp >> 1) * 64;
    const int n0w  = (warp & 1) * 64;

    const int rr  = tid >> 3;             // 0..15
    const int seg = tid & 7;
    const uint32_t sw = (uint32_t)(seg ^ (rr & 7)) << 4;

    const __half* srcs[2] = {Ah, Bh};
    const int r0s[2] = {row0, col0};

#define COPY_CHUNK(KC, BUF) do {                                              \
    _Pragma("unroll")                                                         \
    for (int t = 0; t < 2; t++) {                                             \
        const __half* s_ = srcs[t] +                                          \
            (size_t)(r0s[t] + rr) * DMODEL + (KC) * 64 + seg * 8;             \
        uint32_t d_ = sb + (BUF) * BUFB + t * 16384 + (uint32_t)rr * 128 + sw;\
        _Pragma("unroll")                                                     \
        for (int p = 0; p < 8; p++)                                           \
            cp_async16(d_ + p * 2048, s_ + (size_t)p * 16 * DMODEL);          \
    }                                                                         \
} while (0)

    float acc[4][8][4];
#pragma unroll
    for (int i = 0; i < 4; i++)
#pragma unroll
        for (int j = 0; j < 8; j++)
#pragma unroll
            for (int e = 0; e < 4; e++) acc[i][j][e] = 0.0f;

    const uint32_t xa   = lane & 7;
    const int aSel      = lane >> 4;
    const int bSel      = (lane >> 3) & 1;
    const uint32_t aRow = (uint32_t)(m0w + (lane & 15)) * 128;
    const uint32_t bRow = (uint32_t)(n0w + ((lane >> 4) << 3) + (lane & 7)) * 128;

    COPY_CHUNK(0, 0); CP_COMMIT();
    COPY_CHUNK(1, 1); CP_COMMIT();

    int rslot = 0, cslot = 2;
    for (int kc = 0; kc < 16; kc++) {
        if (kc < 15) { CP_WAIT(1); } else { CP_WAIT(0); }
        __syncthreads();   // single barrier: data for chunk kc visible,
                           // all warps done reading chunk kc-1's buffer
        if (kc + 2 < 16) {
            COPY_CHUNK(kc + 2, cslot);
            CP_COMMIT();
        }

        const uint32_t bufb = sb + (uint32_t)rslot * BUFB;
        const uint32_t aBase = bufb + aRow;
        const uint32_t bBase = bufb + 16384 + bRow;

#pragma unroll
        for (int ks = 0; ks < 4; ks++) {
            const uint32_t ach = (uint32_t)(((2 * ks + aSel) ^ xa) << 4);
            const uint32_t bch = (uint32_t)(((2 * ks + bSel) ^ xa) << 4);

            uint32_t ah[4][4], bh[4][4];
#pragma unroll
            for (int ma = 0; ma < 4; ma++)
                ldsm4(ah[ma], aBase + ma * 2048 + ach);
#pragma unroll
            for (int nb = 0; nb < 4; nb++)
                ldsm4(bh[nb], bBase + nb * 2048 + bch);

#pragma unroll
            for (int ma = 0; ma < 4; ma++)
#pragma unroll
                for (int na = 0; na < 8; na++) {
                    const int nb = na >> 1, sub = (na & 1) * 2;
                    mma16816(acc[ma][na], ah[ma], &bh[nb][sub]);
                }
        }
        rslot = (rslot == 2) ? 0 : rslot + 1;
        cslot = (cslot == 2) ? 0 : cslot + 1;
    }

    // epilogue
    const int g = lane >> 2, tg = lane & 3;
#pragma unroll
    for (int na = 0; na < 8; na++) {
        const int col = col0 + n0w + na * 8 + 2 * tg;
        const float b0 = bias[col], b1 = bias[col + 1];
#pragma unroll
        for (int ma = 0; ma < 4; ma++) {
            const int r = row0 + m0w + ma * 16 + g;
            float v0 = acc[ma][na][0] + b0;
            float v1 = acc[ma][na][1] + b1;
            float v2 = acc[ma][na][2] + b0;
            float v3 = acc[ma][na][3] + b1;
            if (OUT == 0) {
                *(float2*)(Cf + (size_t)r * DMODEL + col) = make_float2(v0, v1);
                *(float2*)(Cf + (size_t)(r + 8) * DMODEL + col) = make_float2(v2, v3);
            } else {
                v0 *= oscale; v1 *= oscale; v2 *= oscale; v3 *= oscale;
                *(__half2*)(Chi + (size_t)r * DMODEL + col) =
                    __floats2half2_rn(v0, v1);
                *(__half2*)(Chi + (size_t)(r + 8) * DMODEL + col) =
                    __floats2half2_rn(v2, v3);
            }
        }
    }
#undef COPY_CHUNK
}

__global__ __launch_bounds__(128, 2) void qkv_mma(const float* __restrict__ bq,
                                                  const float* __restrict__ bk,
                                                  const float* __restrict__ bv) {
    const int z = blockIdx.z;
    const float* bias = (z == 0) ? bq : (z == 1) ? bk : bv;
    const float scale = (z == 0) ? 0.125f * LOG2E : 1.0f;
    mma_gemm_body<2>(g_xh[z], g_wh[z], bias, nullptr, g_ph[z], scale);
}

__global__ __launch_bounds__(128, 2) void out_mma(const float* __restrict__ bo,
                                                  float* __restrict__ out) {
    mma_gemm_body<0>(g_ch, g_wh[3], bo, out, nullptr, 1.0f);
}

// ---------------------------------------------------------------------------
// Tensor-core flash attention, fp16, no-max-shift softmax (exp2 domain).
// Block = 128 q rows; 128 threads / 4 warps (32 q-rows each); 2 CTAs/SM.
// 3-stage KV smem ring -> ONE barrier per key tile.
// smem: Q 16K | 3 stages x (K 8K | V 8K) = 64KB.
// Mask via per-128x64-tile zero flags: all-zero tiles skip LDG + FMA.
// ---------------------------------------------------------------------------
#define ATT_SMEM 65536

__global__ __launch_bounds__(128, 2) void attn_mma(const float* __restrict__ Mask)
{
    extern __shared__ char sm[];
    const uint32_t sb = smem_u32(sm);
    const int tid  = threadIdx.x;
    const int lane = tid & 31;
    const int warp = tid >> 5;        // 0..3
    const int qb = blockIdx.x * 128;
    const int h  = blockIdx.y;
    const int b  = blockIdx.z;

    const int g  = lane >> 2;
    const int tg = lane & 3;
    const uint32_t xa = lane & 7;

    // ---- Q copy (128 rows x 8 segs = 1024 x 16B) ----
#pragma unroll
    for (int i = 0; i < 8; i++) {
        int s_ = tid + i * 128;
        int row = s_ >> 3, sg = s_ & 7;
        const __half* src = g_ph[0] +
            (size_t)(b * SEQ + qb + row) * DMODEL + h * HDIM + sg * 8;
        uint32_t dst = sb + row * 128 + (uint32_t)((sg ^ (row & 7)) << 4);
        cp_async16(dst, src);
    }
    CP_COMMIT();

    const __half* kvsrc[2] = {g_ph[1], g_ph[2]};
#define COPY_KV(T, SLOT) do {                                                 \
    _Pragma("unroll")                                                         \
    for (int i = 0; i < 8; i++) {                                             \
        int s_ = tid + i * 128;                                               \
        int arr = s_ >> 9, rem = s_ & 511;                                    \
        int row = rem >> 3, sg = rem & 7;                                     \
        const __half* src = kvsrc[arr] +                                      \
            (size_t)(b * SEQ + (T) * 64 + row) * DMODEL + h * HDIM + sg * 8;  \
        uint32_t dst = sb + 16384 + (SLOT) * 16384 + arr * 8192 + row * 128 + \
                       (uint32_t)((sg ^ (row & 7)) << 4);                     \
        cp_async16(dst, src);                                                 \
    }                                                                         \
} while (0)

    COPY_KV(0, 0); CP_COMMIT();
    COPY_KV(1, 1); CP_COMMIT();
    CP_WAIT(2);          // Q complete
    __syncthreads();

    // ---- Q fragments (resident): 2 m16 frags per warp ----
    uint32_t qh[2][4][4];
    {
        const int qSel = lane >> 4;
#pragma unroll
        for (int qf = 0; qf < 2; qf++) {
            const uint32_t qRow = sb +
                (uint32_t)(32 * warp + qf * 16 + (lane & 15)) * 128;
#pragma unroll
            for (int ks = 0; ks < 4; ks++) {
                const uint32_t ch = (uint32_t)(((2 * ks + qSel) ^ xa) << 4);
                ldsm4(qh[qf][ks], qRow + ch);
            }
        }
    }

    // ---- state ----
    float o[2][8][4];
#pragma unroll
    for (int qf = 0; qf < 2; qf++)
#pragma unroll
        for (int i = 0; i < 8; i++)
#pragma unroll
            for (int e = 0; e < 4; e++) o[qf][i][e] = 0.0f;
    float lp[2][2] = {{0.0f, 0.0f}, {0.0f, 0.0f}};

    const float* mrow[4];
#pragma unroll
    for (int rg = 0; rg < 4; rg++)
        mrow[rg] = Mask + ((size_t)b * SEQ + (qb + 32 * warp + 8 * rg + g)) * SEQ;
    const unsigned char* mzrow = g_mzero + (b * 16 + blockIdx.x) * 32;

    const uint32_t kRowB = (uint32_t)((((lane >> 4) << 3) + (lane & 7)) * 128);
    const int kSel = (lane >> 3) & 1;
    const uint32_t vRowB = (uint32_t)(((lane & 7) + (((lane >> 3) & 1) << 3)) * 128);
    const int vSel = lane >> 4;

    int rslot = 0, cslot = 2;
    for (int t = 0; t < 32; t++) {
        if (t < 31) { CP_WAIT(1); } else { CP_WAIT(0); }
        __syncthreads();   // single barrier per tile (3-stage ring)
        if (t + 2 < 32) {
            COPY_KV(t + 2, cslot);
            CP_COMMIT();
        }

        const uint32_t stg = sb + 16384 + (uint32_t)rslot * 16384;
        const uint32_t vstg = stg + 8192;

        // ---- S = Q K^T (both q-frags share each K fragment) ----
        float s[2][8][4];
#pragma unroll
        for (int qf = 0; qf < 2; qf++)
#pragma unroll
            for (int i = 0; i < 8; i++)
#pragma unroll
                for (int e = 0; e < 4; e++) s[qf][i][e] = 0.0f;

#pragma unroll
        for (int ks = 0; ks < 4; ks++) {
            const uint32_t kch = (uint32_t)(((2 * ks + kSel) ^ xa) << 4);
#pragma unroll
            for (int np = 0; np < 4; np++) {
                uint32_t kh[4];
                ldsm4(kh, stg + kRowB + np * 2048 + kch);
                mma16816(s[0][2 * np],     qh[0][ks], kh);
                mma16816(s[0][2 * np + 1], qh[0][ks], kh + 2);
                mma16816(s[1][2 * np],     qh[1][ks], kh);
                mma16816(s[1][2 * np + 1], qh[1][ks], kh + 2);
            }
        }

        // ---- softmax: p = ex2(s [+ mask*log2e]); accumulate l; pack P ----
        uint32_t aP[2][4][4];
        if (mzrow[t]) {
#pragma unroll
            for (int qf = 0; qf < 2; qf++) {
                __half2 accA = __floats2half2_rn(0.0f, 0.0f);
                __half2 accB = accA;
#pragma unroll
                for (int nt = 0; nt < 8; nt++) {
                    uint32_t pA = ex2h2(h2_as_u32(
                        __floats2half2_rn(s[qf][nt][0], s[qf][nt][1])));
                    uint32_t pB = ex2h2(h2_as_u32(
                        __floats2half2_rn(s[qf][nt][2], s[qf][nt][3])));
                    accA = __hadd2(accA, u32_as_h2(pA));
                    accB = __hadd2(accB, u32_as_h2(pB));
                    const int ks = nt >> 1, half = nt & 1;
                    aP[qf][ks][2 * half + 0] = pA;
                    aP[qf][ks][2 * half + 1] = pB;
                }
                float2 fa = __half22float2(accA);
                float2 fb = __half22float2(accB);
                lp[qf][0] += fa.x + fa.y;
                lp[qf][1] += fb.x + fb.y;
            }
        } else {
            const int kt0 = t * 64;
#pragma unroll
            for (int qf = 0; qf < 2; qf++) {
#pragma unroll
                for (int nt = 0; nt < 8; nt++) {
                    const int kcol = kt0 + 8 * nt + 2 * tg;
                    float2 q0 = *(const float2*)(mrow[2 * qf] + kcol);
                    float2 q1 = *(const float2*)(mrow[2 * qf + 1] + kcol);
                    float p0 = ex2f(fmaf(q0.x, LOG2E, s[qf][nt][0]));
                    float p1 = ex2f(fmaf(q0.y, LOG2E, s[qf][nt][1]));
                    float p2 = ex2f(fmaf(q1.x, LOG2E, s[qf][nt][2]));
                    float p3 = ex2f(fmaf(q1.y, LOG2E, s[qf][nt][3]));
                    lp[qf][0] += p0 + p1;
                    lp[qf][1] += p2 + p3;
                    const int ks = nt >> 1, half = nt & 1;
                    aP[qf][ks][2 * half + 0] = h2_as_u32(__floats2half2_rn(p0, p1));
                    aP[qf][ks][2 * half + 1] = h2_as_u32(__floats2half2_rn(p2, p3));
                }
            }
        }

        // ---- O += P V (both q-frags share each V fragment) ----
#pragma unroll
        for (int ks = 0; ks < 4; ks++) {
#pragma unroll
            for (int np = 0; np < 4; np++) {
                const uint32_t vch = (uint32_t)(((2 * np + vSel) ^ xa) << 4);
                uint32_t vh[4];
                ldsm4t(vh, vstg + vRowB + ks * 2048 + vch);
                mma16816(o[0][2 * np],     aP[0][ks], vh);
                mma16816(o[0][2 * np + 1], aP[0][ks], vh + 2);
                mma16816(o[1][2 * np],     aP[1][ks], vh);
                mma16816(o[1][2 * np + 1], aP[1][ks], vh + 2);
            }
        }

        rslot = (rslot == 2) ? 0 : rslot + 1;
        cslot = (cslot == 2) ? 0 : cslot + 1;
    }

    // ---- final l reduction + epilogue (ctx fp16) ----
#pragma unroll
    for (int qf = 0; qf < 2; qf++)
#pragma unroll
        for (int r = 0; r < 2; r++) {
            lp[qf][r] += __shfl_xor_sync(0xffffffffu, lp[qf][r], 1);
            lp[qf][r] += __shfl_xor_sync(0xffffffffu, lp[qf][r], 2);
        }

#pragma unroll
    for (int qf = 0; qf < 2; qf++) {
        const float inv0 = 1.0f / lp[qf][0], inv1 = 1.0f / lp[qf][1];
        const size_t obase =
            (size_t)(b * SEQ + qb + 32 * warp + qf * 16) * DMODEL + h * HDIM;
#pragma unroll
        for (int nt = 0; nt < 8; nt++) {
            const int col = 8 * nt + 2 * tg;
            *(__half2*)(g_ch + obase + (size_t)g * DMODEL + col) =
                __floats2half2_rn(o[qf][nt][0] * inv0, o[qf][nt][1] * inv0);
            *(__half2*)(g_ch + obase + (size_t)(g + 8) * DMODEL + col) =
                __floats2half2_rn(o[qf][nt][2] * inv1, o[qf][nt][3] * inv1);
        }
    }
#undef COPY_KV
}

// ---------------------------------------------------------------------------
// Launch
// ---------------------------------------------------------------------------
extern "C" void kernel_launch(void* const* d_in, const int* in_sizes, int n_in,
                              void* d_out, int out_size)
{
    const float* query = (const float*)d_in[0];
    const float* key   = (const float*)d_in[1];
    const float* value = (const float*)d_in[2];
    const float* mask  = (const float*)d_in[3];
    const float* WQ_w  = (const float*)d_in[4];
    const float* WQ_b  = (const float*)d_in[5];
    const float* WK_w  = (const float*)d_in[6];
    const float* WK_b  = (const float*)d_in[7];
    const float* WV_w  = (const float*)d_in[8];
    const float* WV_b  = (const float*)d_in[9];
    const float* WO_w  = (const float*)d_in[10];
    const float* WO_b  = (const float*)d_in[11];
    float* out = (float*)d_out;

    cudaFuncSetAttribute(qkv_mma, cudaFuncAttributeMaxDynamicSharedMemorySize, MMA_SMEM);
    cudaFuncSetAttribute(out_mma, cudaFuncAttributeMaxDynamicSharedMemorySize, MMA_SMEM);
    cudaFuncSetAttribute(attn_mma, cudaFuncAttributeMaxDynamicSharedMemorySize, ATT_SMEM);

    // 1) convert inputs + weights to fp16 (one launch); mask tile flags
    prep<<<dim3(MTOT * DMODEL / 1024, 7), 256>>>(query, key, value,
                                                 WQ_w, WK_w, WV_w, WO_w);
    mask_flags<<<dim3(32, 16, BATCH), 256>>>(mask);

    // 2) QKV projections (tensor cores), fp16 outputs
    qkv_mma<<<dim3(DMODEL / 128, MTOT / 128, 3), 128, MMA_SMEM>>>(WQ_b, WK_b, WV_b);

    // 3) tensor-core flash attention -> ctx fp16 (2 CTAs/SM)
    attn_mma<<<dim3(SEQ / 128, NHEAD, BATCH), 128, ATT_SMEM>>>(mask);

    // 4) output projection (tensor cores), fp32 out
    out_mma<<<dim3(DMODEL / 128, MTOT / 128), 128, MMA_SMEM>>>(WO_b, out);
}

// round 15
// speedup vs baseline: 1.1842x; 1.1842x over previous
#include <cuda_runtime.h>
#include <cuda_fp16.h>
#include <stdint.h>
#include <math.h>

// Problem constants (fixed shapes)
#define BATCH   2
#define SEQ     2048
#define DMODEL  1024
#define NHEAD   16
#define HDIM    64
#define MTOT    (BATCH*SEQ)   // 4096

#define LOG2E   1.4426950408889634f

// ---------------- scratch (__device__ globals; no allocs allowed) ----------
__device__ __half g_xh[3][MTOT * DMODEL];   // q,k,v input activations (fp16)
__device__ __half g_wh[4][DMODEL * DMODEL]; // WQ,WK,WV,WO (fp16)
__device__ __half g_ph[3][MTOT * DMODEL];   // projected Q,K,V (Q pre-scaled)
__device__ __half g_ch[MTOT * DMODEL];      // ctx (fp16)
__device__ unsigned char g_mzero[BATCH * 16 * 32]; // 1 = 128x64 mask tile all-zero

// ---------------- portable PTX helpers -------------------------------------
__device__ __forceinline__ uint32_t smem_u32(const void* p) {
    uint32_t a;
    asm("{ .reg .u64 t; cvta.to.shared.u64 t, %1; cvt.u32.u64 %0, t; }"
        : "=r"(a) : "l"(p));
    return a;
}
__device__ __forceinline__ void cp_async16(uint32_t dst, const void* src) {
    asm volatile("cp.async.cg.shared.global [%0], [%1], 16;"
                 :: "r"(dst), "l"(src));
}
#define CP_COMMIT()  asm volatile("cp.async.commit_group;" ::: "memory")
#define CP_WAIT(N)   asm volatile("cp.async.wait_group %0;" :: "n"(N) : "memory")

__device__ __forceinline__ void ldsm4(uint32_t* r, uint32_t addr) {
    asm volatile("ldmatrix.sync.aligned.m8n8.x4.shared.b16 {%0,%1,%2,%3}, [%4];"
                 : "=r"(r[0]), "=r"(r[1]), "=r"(r[2]), "=r"(r[3]) : "r"(addr));
}
__device__ __forceinline__ void ldsm4t(uint32_t* r, uint32_t addr) {
    asm volatile("ldmatrix.sync.aligned.m8n8.x4.trans.shared.b16 {%0,%1,%2,%3}, [%4];"
                 : "=r"(r[0]), "=r"(r[1]), "=r"(r[2]), "=r"(r[3]) : "r"(addr));
}
__device__ __forceinline__ void mma16816(float* c, const uint32_t* a,
                                         const uint32_t* b) {
    asm volatile(
        "mma.sync.aligned.m16n8k16.row.col.f32.f16.f16.f32 "
        "{%0,%1,%2,%3}, {%4,%5,%6,%7}, {%8,%9}, {%0,%1,%2,%3};"
        : "+f"(c[0]), "+f"(c[1]), "+f"(c[2]), "+f"(c[3])
        : "r"(a[0]), "r"(a[1]), "r"(a[2]), "r"(a[3]), "r"(b[0]), "r"(b[1]));
}
__device__ __forceinline__ float ex2f(float x) {
    float r;
    asm("ex2.approx.f32 %0, %1;" : "=f"(r) : "f"(x));
    return r;
}
__device__ __forceinline__ uint32_t ex2h2(uint32_t x) {
    uint32_t r;
    asm("ex2.approx.f16x2 %0, %1;" : "=r"(r) : "r"(x));
    return r;
}
__device__ __forceinline__ uint32_t h2_as_u32(__half2 v) {
    return *reinterpret_cast<uint32_t*>(&v);
}
__device__ __forceinline__ __half2 u32_as_h2(uint32_t v) {
    return *reinterpret_cast<__half2*>(&v);
}

// ---------------------------------------------------------------------------
// fp32 -> fp16 conversion (fused: z<3 activations [4096 blocks],
// z>=3 weights [first 1024 blocks])
// ---------------------------------------------------------------------------
__global__ __launch_bounds__(256) void prep(const float* __restrict__ q,
                                            const float* __restrict__ k,
                                            const float* __restrict__ v,
                                            const float* __restrict__ wq,
                                            const float* __restrict__ wk,
                                            const float* __restrict__ wv,
                                            const float* __restrict__ wo) {
    const int z = blockIdx.y;
    if (z >= 3 && blockIdx.x >= DMODEL * DMODEL / 1024) return;
    const float* srcs[7] = {q, k, v, wq, wk, wv, wo};
    __half* dsts[7] = {g_xh[0], g_xh[1], g_xh[2],
                       g_wh[0], g_wh[1], g_wh[2], g_wh[3]};
    const float* s = srcs[z];
    __half* d = dsts[z];
    int i = (blockIdx.x * 256 + threadIdx.x) * 4;
    float4 x = *(const float4*)(s + i);
    *(__half2*)(d + i)     = __floats2half2_rn(x.x, x.y);
    *(__half2*)(d + i + 2) = __floats2half2_rn(x.z, x.w);
}

// ---------------------------------------------------------------------------
// Per-tile mask zero-flag: g_mzero[b][qt][kt] = (128x64 tile entirely 0.0f)
// ---------------------------------------------------------------------------
__global__ __launch_bounds__(256) void mask_flags(const float* __restrict__ mask) {
    const int kt = blockIdx.x, qt = blockIdx.y, b = blockIdx.z;
    const int tid = threadIdx.x;
    const int row = tid >> 2;
    const int c0  = (tid & 3) * 16;
    int nz = 0;
#pragma unroll
    for (int half = 0; half < 2; half++) {
        const float* p = mask + ((size_t)b * SEQ + qt * 128 + half * 64 + row) * SEQ
                         + kt * 64 + c0;
#pragma unroll
        for (int i = 0; i < 4; i++) {
            float4 v = *(const float4*)(p + i * 4);
            nz |= (v.x != 0.0f) | (v.y != 0.0f) | (v.z != 0.0f) | (v.w != 0.0f);
        }
    }
    nz = __syncthreads_or(nz);
    if (tid == 0)
        g_mzero[(b * 16 + qt) * 32 + kt] = (unsigned char)(nz == 0);
}

// ---------------------------------------------------------------------------
// Warp-MMA GEMM (NT): C[128,128]/CTA = A[M,K] * B[N,K]^T + bias, pure fp16.
// 256 threads / 8 warps (2x4), warp tile 64x32 (best measured per-MMA rate).
// OUT: 0 = fp32 + bias; 2 = f16 * oscale.
// smem/stage: A 16K | B 16K = 32KB, double buffered = 64KB. 2 CTAs/SM.
// ---------------------------------------------------------------------------
#define BUFB     32768
#define MMA_SMEM (2 * BUFB)   // 65536

template<int OUT>
__device__ __forceinline__ void mma_gemm_body(
    const __half* __restrict__ Ah,
    const __half* __restrict__ Bh,
    const float* __restrict__ bias,
    float* __restrict__ Cf,
    __half* __restrict__ Chi,
    float oscale)
{
    extern __shared__ char sm[];
    const uint32_t sb = smem_u32(sm);
    const int tid  = threadIdx.x;
    const int lane = tid & 31;
    const int warp = tid >> 5;            // 0..7
    const int row0 = blockIdx.y * 128;
    const int col0 = blockIdx.x * 128;
    const int m0w  = (warp >> 2) * 64;
    const int n0w  = (warp & 3) * 32;

    const int rr  = tid >> 3;             // 0..31
    const int seg = tid & 7;
    const uint32_t sw = (uint32_t)(seg ^ (rr & 7)) << 4;

    const __half* srcs[2] = {Ah, Bh};
    const int r0s[2] = {row0, col0};

#define COPY_CHUNK(KC, BUF) do {                                              \
    _Pragma("unroll")                                                         \
    for (int t = 0; t < 2; t++) {                                             \
        const __half* s_ = srcs[t] +                                          \
            (size_t)(r0s[t] + rr) * DMODEL + (KC) * 64 + seg * 8;             \
        uint32_t d_ = sb + (BUF) * BUFB + t * 16384 + (uint32_t)rr * 128 + sw;\
        _Pragma("unroll")                                                     \
        for (int p = 0; p < 4; p++)                                           \
            cp_async16(d_ + p * 4096, s_ + (size_t)p * 32 * DMODEL);          \
    }                                                                         \
} while (0)

    float acc[4][4][4];
#pragma unroll
    for (int i = 0; i < 4; i++)
#pragma unroll
        for (int j = 0; j < 4; j++)
#pragma unroll
            for (int e = 0; e < 4; e++) acc[i][j][e] = 0.0f;

    const uint32_t xa   = lane & 7;
    const int aSel      = lane >> 4;
    const int bSel      = (lane >> 3) & 1;
    const uint32_t aRow = (uint32_t)(m0w + (lane & 15)) * 128;
    const uint32_t bRow = (uint32_t)(n0w + ((lane >> 4) << 3) + (lane & 7)) * 128;

    COPY_CHUNK(0, 0);
    CP_COMMIT();

    for (int kc = 0; kc < 16; kc++) {
        if (kc < 15) {
            COPY_CHUNK(kc + 1, (kc + 1) & 1);
            CP_COMMIT();
            CP_WAIT(1);
        } else {
            CP_WAIT(0);
        }
        __syncthreads();

        const uint32_t bufb = sb + (uint32_t)(kc & 1) * BUFB;
        const uint32_t aBase = bufb + aRow;
        const uint32_t bBase = bufb + 16384 + bRow;

#pragma unroll
        for (int ks = 0; ks < 4; ks++) {
            const uint32_t ach = (uint32_t)(((2 * ks + aSel) ^ xa) << 4);
            const uint32_t bch = (uint32_t)(((2 * ks + bSel) ^ xa) << 4);

            uint32_t ah[4][4], bh[2][4];
#pragma unroll
            for (int ma = 0; ma < 4; ma++)
                ldsm4(ah[ma], aBase + ma * 2048 + ach);
#pragma unroll
            for (int nb = 0; nb < 2; nb++)
                ldsm4(bh[nb], bBase + nb * 2048 + bch);

#pragma unroll
            for (int ma = 0; ma < 4; ma++)
#pragma unroll
                for (int na = 0; na < 4; na++) {
                    const int nb = na >> 1, sub = (na & 1) * 2;
                    mma16816(acc[ma][na], ah[ma], &bh[nb][sub]);
                }
        }
        __syncthreads();
    }

    // epilogue
    const int g = lane >> 2, tg = lane & 3;
#pragma unroll
    for (int na = 0; na < 4; na++) {
        const int col = col0 + n0w + na * 8 + 2 * tg;
        const float b0 = bias[col], b1 = bias[col + 1];
#pragma unroll
        for (int ma = 0; ma < 4; ma++) {
            const int r = row0 + m0w + ma * 16 + g;
            float v0 = acc[ma][na][0] + b0;
            float v1 = acc[ma][na][1] + b1;
            float v2 = acc[ma][na][2] + b0;
            float v3 = acc[ma][na][3] + b1;
            if (OUT == 0) {
                *(float2*)(Cf + (size_t)r * DMODEL + col) = make_float2(v0, v1);
                *(float2*)(Cf + (size_t)(r + 8) * DMODEL + col) = make_float2(v2, v3);
            } else {
                v0 *= oscale; v1 *= oscale; v2 *= oscale; v3 *= oscale;
                *(__half2*)(Chi + (size_t)r * DMODEL + col) =
                    __floats2half2_rn(v0, v1);
                *(__half2*)(Chi + (size_t)(r + 8) * DMODEL + col) =
                    __floats2half2_rn(v2, v3);
            }
        }
    }
#undef COPY_CHUNK
}

__global__ __launch_bounds__(256, 2) void qkv_mma(const float* __restrict__ bq,
                                                  const float* __restrict__ bk,
                                                  const float* __restrict__ bv) {
    const int z = blockIdx.z;
    const float* bias = (z == 0) ? bq : (z == 1) ? bk : bv;
    const float scale = (z == 0) ? 0.125f * LOG2E : 1.0f;
    mma_gemm_body<2>(g_xh[z], g_wh[z], bias, nullptr, g_ph[z], scale);
}

__global__ __launch_bounds__(256, 2) void out_mma(const float* __restrict__ bo,
                                                  float* __restrict__ out) {
    mma_gemm_body<0>(g_ch, g_wh[3], bo, out, nullptr, 1.0f);
}

// ---------------------------------------------------------------------------
// Tensor-core flash attention (exact R11 config: best measured).
// Block = 128 q rows; 128 threads / 4 warps (32 q-rows each); 2 CTAs/SM.
// smem: Q 16K | 2 stages x (K 8K | V 8K) = 48KB.
// Mask via per-128x64-tile zero flags.
// ---------------------------------------------------------------------------
#define ATT_SMEM 49152

__global__ __launch_bounds__(128, 2) void attn_mma(const float* __restrict__ Mask)
{
    extern __shared__ char sm[];
    const uint32_t sb = smem_u32(sm);
    const int tid  = threadIdx.x;
    const int lane = tid & 31;
    const int warp = tid >> 5;        // 0..3
    const int qb = blockIdx.x * 128;
    const int h  = blockIdx.y;
    const int b  = blockIdx.z;

    const int g  = lane >> 2;
    const int tg = lane & 3;
    const uint32_t xa = lane & 7;

    // ---- Q copy (128 rows x 8 segs = 1024 x 16B) ----
#pragma unroll
    for (int i = 0; i < 8; i++) {
        int s_ = tid + i * 128;
        int row = s_ >> 3, sg = s_ & 7;
        const __half* src = g_ph[0] +
            (size_t)(b * SEQ + qb + row) * DMODEL + h * HDIM + sg * 8;
        uint32_t dst = sb + row * 128 + (uint32_t)((sg ^ (row & 7)) << 4);
        cp_async16(dst, src);
    }
    CP_COMMIT();

    const __half* kvsrc[2] = {g_ph[1], g_ph[2]};
#define COPY_KV(T, SLOT) do {                                                 \
    _Pragma("unroll")                                                         \
    for (int i = 0; i < 8; i++) {                                             \
        int s_ = tid + i * 128;                                               \
        int arr = s_ >> 9, rem = s_ & 511;                                    \
        int row = rem >> 3, sg = rem & 7;                                     \
        const __half* src = kvsrc[arr] +                                      \
            (size_t)(b * SEQ + (T) * 64 + row) * DMODEL + h * HDIM + sg * 8;  \
        uint32_t dst = sb + 16384 + (SLOT) * 16384 + arr * 8192 + row * 128 + \
                       (uint32_t)((sg ^ (row & 7)) << 4);                     \
        cp_async16(dst, src);                                                 \
    }                                                                         \
} while (0)

    COPY_KV(0, 0); CP_COMMIT();
    COPY_KV(1, 1); CP_COMMIT();
    CP_WAIT(2);          // Q complete
    __syncthreads();

    // ---- Q fragments (resident): 2 m16 frags per warp ----
    uint32_t qh[2][4][4];
    {
        const int qSel = lane >> 4;
#pragma unroll
        for (int qf = 0; qf < 2; qf++) {
            const uint32_t qRow = sb +
                (uint32_t)(32 * warp + qf * 16 + (lane & 15)) * 128;
#pragma unroll
            for (int ks = 0; ks < 4; ks++) {
                const uint32_t ch = (uint32_t)(((2 * ks + qSel) ^ xa) << 4);
                ldsm4(qh[qf][ks], qRow + ch);
            }
        }
    }

    // ---- state ----
    float o[2][8][4];
#pragma unroll
    for (int qf = 0; qf < 2; qf++)
#pragma unroll
        for (int i = 0; i < 8; i++)
#pragma unroll
            for (int e = 0; e < 4; e++) o[qf][i][e] = 0.0f;
    float lp[2][2] = {{0.0f, 0.0f}, {0.0f, 0.0f}};

    const float* mrow[4];
#pragma unroll
    for (int rg = 0; rg < 4; rg++)
        mrow[rg] = Mask + ((size_t)b * SEQ + (qb + 32 * warp + 8 * rg + g)) * SEQ;
    const unsigned char* mzrow = g_mzero + (b * 16 + blockIdx.x) * 32;

    const uint32_t kRowB = (uint32_t)((((lane >> 4) << 3) + (lane & 7)) * 128);
    const int kSel = (lane >> 3) & 1;
    const uint32_t vRowB = (uint32_t)(((lane & 7) + (((lane >> 3) & 1) << 3)) * 128);
    const int vSel = lane >> 4;

    for (int t = 0; t < 32; t++) {
        if (t < 31) { CP_WAIT(1); } else { CP_WAIT(0); }
        __syncthreads();
        const uint32_t stg = sb + 16384 + (uint32_t)(t & 1) * 16384;

        // ---- S = Q K^T (both q-frags share each K fragment) ----
        float s[2][8][4];
#pragma unroll
        for (int qf = 0; qf < 2; qf++)
#pragma unroll
            for (int i = 0; i < 8; i++)
#pragma unroll
                for (int e = 0; e < 4; e++) s[qf][i][e] = 0.0f;

#pragma unroll
        for (int ks = 0; ks < 4; ks++) {
            const uint32_t kch = (uint32_t)(((2 * ks + kSel) ^ xa) << 4);
#pragma unroll
            for (int np = 0; np < 4; np++) {
                uint32_t kh[4];
                ldsm4(kh, stg + kRowB + np * 2048 + kch);
                mma16816(s[0][2 * np],     qh[0][ks], kh);
                mma16816(s[0][2 * np + 1], qh[0][ks], kh + 2);
                mma16816(s[1][2 * np],     qh[1][ks], kh);
                mma16816(s[1][2 * np + 1], qh[1][ks], kh + 2);
            }
        }

        // ---- softmax: p = ex2(s [+ mask*log2e]); accumulate l; pack P ----
        uint32_t aP[2][4][4];
        if (mzrow[t]) {
#pragma unroll
            for (int qf = 0; qf < 2; qf++) {
                __half2 accA = __floats2half2_rn(0.0f, 0.0f);
                __half2 accB = accA;
#pragma unroll
                for (int nt = 0; nt < 8; nt++) {
                    uint32_t pA = ex2h2(h2_as_u32(
                        __floats2half2_rn(s[qf][nt][0], s[qf][nt][1])));
                    uint32_t pB = ex2h2(h2_as_u32(
                        __floats2half2_rn(s[qf][nt][2], s[qf][nt][3])));
                    accA = __hadd2(accA, u32_as_h2(pA));
                    accB = __hadd2(accB, u32_as_h2(pB));
                    const int ks = nt >> 1, half = nt & 1;
                    aP[qf][ks][2 * half + 0] = pA;
                    aP[qf][ks][2 * half + 1] = pB;
                }
                float2 fa = __half22float2(accA);
                float2 fb = __half22float2(accB);
                lp[qf][0] += fa.x + fa.y;
                lp[qf][1] += fb.x + fb.y;
            }
        } else {
            const int kt0 = t * 64;
#pragma unroll
            for (int qf = 0; qf < 2; qf++) {
#pragma unroll
                for (int nt = 0; nt < 8; nt++) {
                    const int kcol = kt0 + 8 * nt + 2 * tg;
                    float2 q0 = *(const float2*)(mrow[2 * qf] + kcol);
                    float2 q1 = *(const float2*)(mrow[2 * qf + 1] + kcol);
                    float p0 = ex2f(fmaf(q0.x, LOG2E, s[qf][nt][0]));
                    float p1 = ex2f(fmaf(q0.y, LOG2E, s[qf][nt][1]));
                    float p2 = ex2f(fmaf(q1.x, LOG2E, s[qf][nt][2]));
                    float p3 = ex2f(fmaf(q1.y, LOG2E, s[qf][nt][3]));
                    lp[qf][0] += p0 + p1;
                    lp[qf][1] += p2 + p3;
                    const int ks = nt >> 1, half = nt & 1;
                    aP[qf][ks][2 * half + 0] = h2_as_u32(__floats2half2_rn(p0, p1));
                    aP[qf][ks][2 * half + 1] = h2_as_u32(__floats2half2_rn(p2, p3));
                }
            }
        }

        // ---- O += P V (both q-frags share each V fragment) ----
#pragma unroll
        for (int ks = 0; ks < 4; ks++) {
#pragma unroll
            for (int np = 0; np < 4; np++) {
                const uint32_t vch = (uint32_t)(((2 * np + vSel) ^ xa) << 4);
                uint32_t vh[4];
                ldsm4t(vh, stg + 8192 + vRowB + ks * 2048 + vch);
                mma16816(o[0][2 * np],     aP[0][ks], vh);
                mma16816(o[0][2 * np + 1], aP[0][ks], vh + 2);
                mma16816(o[1][2 * np],     aP[1][ks], vh);
                mma16816(o[1][2 * np + 1], aP[1][ks], vh + 2);
            }
        }

        __syncthreads();
        if (t + 2 < 32) { COPY_KV(t + 2, t & 1); CP_COMMIT(); }
    }

    // ---- final l reduction + epilogue (ctx fp16) ----
#pragma unroll
    for (int qf = 0; qf < 2; qf++)
#pragma unroll
        for (int r = 0; r < 2; r++) {
            lp[qf][r] += __shfl_xor_sync(0xffffffffu, lp[qf][r], 1);
            lp[qf][r] += __shfl_xor_sync(0xffffffffu, lp[qf][r], 2);
        }

#pragma unroll
    for (int qf = 0; qf < 2; qf++) {
        const float inv0 = 1.0f / lp[qf][0], inv1 = 1.0f / lp[qf][1];
        const size_t obase =
            (size_t)(b * SEQ + qb + 32 * warp + qf * 16) * DMODEL + h * HDIM;
#pragma unroll
        for (int nt = 0; nt < 8; nt++) {
            const int col = 8 * nt + 2 * tg;
            *(__half2*)(g_ch + obase + (size_t)g * DMODEL + col) =
                __floats2half2_rn(o[qf][nt][0] * inv0, o[qf][nt][1] * inv0);
            *(__half2*)(g_ch + obase + (size_t)(g + 8) * DMODEL + col) =
                __floats2half2_rn(o[qf][nt][2] * inv1, o[qf][nt][3] * inv1);
        }
    }
#undef COPY_KV
}

// ---------------------------------------------------------------------------
// Launch
// ---------------------------------------------------------------------------
extern "C" void kernel_launch(void* const* d_in, const int* in_sizes, int n_in,
                              void* d_out, int out_size)
{
    const float* query = (const float*)d_in[0];
    const float* key   = (const float*)d_in[1];
    const float* value = (const float*)d_in[2];
    const float* mask  = (const float*)d_in[3];
    const float* WQ_w  = (const float*)d_in[4];
    const float* WQ_b  = (const float*)d_in[5];
    const float* WK_w  = (const float*)d_in[6];
    const float* WK_b  = (const float*)d_in[7];
    const float* WV_w  = (const float*)d_in[8];
    const float* WV_b  = (const float*)d_in[9];
    const float* WO_w  = (const float*)d_in[10];
    const float* WO_b  = (const float*)d_in[11];
    float* out = (float*)d_out;

    cudaFuncSetAttribute(qkv_mma, cudaFuncAttributeMaxDynamicSharedMemorySize, MMA_SMEM);
    cudaFuncSetAttribute(out_mma, cudaFuncAttributeMaxDynamicSharedMemorySize, MMA_SMEM);
    cudaFuncSetAttribute(attn_mma, cudaFuncAttributeMaxDynamicSharedMemorySize, ATT_SMEM);

    // 1) convert inputs + weights to fp16 (one launch); mask tile flags
    prep<<<dim3(MTOT * DMODEL / 1024, 7), 256>>>(query, key, value,
                                                 WQ_w, WK_w, WV_w, WO_w);
    mask_flags<<<dim3(32, 16, BATCH), 256>>>(mask);

    // 2) QKV projections (tensor cores), fp16 outputs
    qkv_mma<<<dim3(DMODEL / 128, MTOT / 128, 3), 256, MMA_SMEM>>>(WQ_b, WK_b, WV_b);

    // 3) tensor-core flash attention -> ctx fp16 (2 CTAs/SM)
    attn_mma<<<dim3(SEQ / 128, NHEAD, BATCH), 128, ATT_SMEM>>>(mask);

    // 4) output projection (tensor cores), fp32 out
    out_mma<<<dim3(DMODEL / 128, MTOT / 128), 256, MMA_SMEM>>>(WO_b, out);
}

// round 16
// speedup vs baseline: 1.4253x; 1.2036x over previous
#include <cuda_runtime.h>
#include <cuda_fp16.h>
#include <stdint.h>
#include <math.h>

// Problem constants (fixed shapes)
#define BATCH   2
#define SEQ     2048
#define DMODEL  1024
#define NHEAD   16
#define HDIM    64
#define MTOT    (BATCH*SEQ)   // 4096

#define LOG2E   1.4426950408889634f

// ---------------- scratch (__device__ globals; no allocs allowed) ----------
__device__ __half g_xh[3][MTOT * DMODEL];   // q,k,v input activations (fp16)
__device__ __half g_wh[4][DMODEL * DMODEL]; // WQ,WK,WV,WO (fp16)
__device__ __half g_ph[3][MTOT * DMODEL];   // projected Q,K,V (Q pre-scaled)
__device__ __half g_ch[MTOT * DMODEL];      // ctx (fp16)
__device__ unsigned char g_mzero[BATCH * 16 * 32]; // 1 = 128x64 mask tile all-zero

// ---------------- portable PTX helpers -------------------------------------
__device__ __forceinline__ uint32_t smem_u32(const void* p) {
    uint32_t a;
    asm("{ .reg .u64 t; cvta.to.shared.u64 t, %1; cvt.u32.u64 %0, t; }"
        : "=r"(a) : "l"(p));
    return a;
}
__device__ __forceinline__ void cp_async16(uint32_t dst, const void* src) {
    asm volatile("cp.async.cg.shared.global [%0], [%1], 16;"
                 :: "r"(dst), "l"(src));
}
#define CP_COMMIT()  asm volatile("cp.async.commit_group;" ::: "memory")
#define CP_WAIT(N)   asm volatile("cp.async.wait_group %0;" :: "n"(N) : "memory")

__device__ __forceinline__ void ldsm4(uint32_t* r, uint32_t addr) {
    asm volatile("ldmatrix.sync.aligned.m8n8.x4.shared.b16 {%0,%1,%2,%3}, [%4];"
                 : "=r"(r[0]), "=r"(r[1]), "=r"(r[2]), "=r"(r[3]) : "r"(addr));
}
__device__ __forceinline__ void ldsm4t(uint32_t* r, uint32_t addr) {
    asm volatile("ldmatrix.sync.aligned.m8n8.x4.trans.shared.b16 {%0,%1,%2,%3}, [%4];"
                 : "=r"(r[0]), "=r"(r[1]), "=r"(r[2]), "=r"(r[3]) : "r"(addr));
}
__device__ __forceinline__ void mma16816(float* c, const uint32_t* a,
                                         const uint32_t* b) {
    asm volatile(
        "mma.sync.aligned.m16n8k16.row.col.f32.f16.f16.f32 "
        "{%0,%1,%2,%3}, {%4,%5,%6,%7}, {%8,%9}, {%0,%1,%2,%3};"
        : "+f"(c[0]), "+f"(c[1]), "+f"(c[2]), "+f"(c[3])
        : "r"(a[0]), "r"(a[1]), "r"(a[2]), "r"(a[3]), "r"(b[0]), "r"(b[1]));
}
__device__ __forceinline__ float ex2f(float x) {
    float r;
    asm("ex2.approx.f32 %0, %1;" : "=f"(r) : "f"(x));
    return r;
}
__device__ __forceinline__ uint32_t ex2h2(uint32_t x) {
    uint32_t r;
    asm("ex2.approx.f16x2 %0, %1;" : "=r"(r) : "r"(x));
    return r;
}
__device__ __forceinline__ uint32_t h2_as_u32(__half2 v) {
    return *reinterpret_cast<uint32_t*>(&v);
}
__device__ __forceinline__ __half2 u32_as_h2(uint32_t v) {
    return *reinterpret_cast<__half2*>(&v);
}

// ---------------------------------------------------------------------------
// fp32 -> fp16 conversion kernels (separate, as in best-measured R11)
// ---------------------------------------------------------------------------
__global__ __launch_bounds__(256) void split_act(const float* __restrict__ q,
                                                 const float* __restrict__ k,
                                                 const float* __restrict__ v) {
    int z = blockIdx.y;
    const float* s = (z == 0) ? q : (z == 1) ? k : v;
    int i = (blockIdx.x * 256 + threadIdx.x) * 4;
    float4 x = *(const float4*)(s + i);
    *(__half2*)(g_xh[z] + i)     = __floats2half2_rn(x.x, x.y);
    *(__half2*)(g_xh[z] + i + 2) = __floats2half2_rn(x.z, x.w);
}

__global__ __launch_bounds__(256) void split_w(const float* __restrict__ wq,
                                               const float* __restrict__ wk,
                                               const float* __restrict__ wv,
                                               const float* __restrict__ wo) {
    int z = blockIdx.y;
    const float* s = (z == 0) ? wq : (z == 1) ? wk : (z == 2) ? wv : wo;
    int i = (blockIdx.x * 256 + threadIdx.x) * 4;
    float4 x = *(const float4*)(s + i);
    *(__half2*)(g_wh[z] + i)     = __floats2half2_rn(x.x, x.y);
    *(__half2*)(g_wh[z] + i + 2) = __floats2half2_rn(x.z, x.w);
}

// ---------------------------------------------------------------------------
// Per-tile mask zero-flag: g_mzero[b][qt][kt] = (128x64 tile entirely 0.0f)
// ---------------------------------------------------------------------------
__global__ __launch_bounds__(256) void mask_flags(const float* __restrict__ mask) {
    const int kt = blockIdx.x, qt = blockIdx.y, b = blockIdx.z;
    const int tid = threadIdx.x;
    const int row = tid >> 2;
    const int c0  = (tid & 3) * 16;
    int nz = 0;
#pragma unroll
    for (int half = 0; half < 2; half++) {
        const float* p = mask + ((size_t)b * SEQ + qt * 128 + half * 64 + row) * SEQ
                         + kt * 64 + c0;
#pragma unroll
        for (int i = 0; i < 4; i++) {
            float4 v = *(const float4*)(p + i * 4);
            nz |= (v.x != 0.0f) | (v.y != 0.0f) | (v.z != 0.0f) | (v.w != 0.0f);
        }
    }
    nz = __syncthreads_or(nz);
    if (tid == 0)
        g_mzero[(b * 16 + qt) * 32 + kt] = (unsigned char)(nz == 0);
}

// ---------------------------------------------------------------------------
// QKV GEMM (NT): C[128,64]/CTA = A[M,K] * B[N,K]^T + bias, pure fp16.
// 128 threads / 4 warps (2x2), warp tile 64x32. ~130 regs -> 3 CTAs/SM.
// smem/stage: A 16K | B 8K = 24KB, double buffered = 48KB (3x48=144K <= 228K).
// ---------------------------------------------------------------------------
#define QBUFB    24576
#define QKV_SMEM (2 * QBUFB)   // 49152

__global__ __launch_bounds__(128, 3) void qkv_mma(const float* __restrict__ bq,
                                                  const float* __restrict__ bk,
                                                  const float* __restrict__ bv) {
    const int z = blockIdx.z;
    const float* bias = (z == 0) ? bq : (z == 1) ? bk : bv;
    const float oscale = (z == 0) ? 0.125f * LOG2E : 1.0f;
    const __half* Ah = g_xh[z];
    const __half* Bh = g_wh[z];
    __half* Chi = g_ph[z];

    extern __shared__ char sm[];
    const uint32_t sb = smem_u32(sm);
    const int tid  = threadIdx.x;
    const int lane = tid & 31;
    const int warp = tid >> 5;            // 0..3
    const int row0 = blockIdx.y * 128;
    const int col0 = blockIdx.x * 64;
    const int m0w  = (warp >> 1) * 64;
    const int n0w  = (warp & 1) * 32;

    const int rr  = tid >> 3;             // 0..15
    const int seg = tid & 7;
    const uint32_t sw = (uint32_t)(seg ^ (rr & 7)) << 4;

#define QCOPY_CHUNK(KC, BUF) do {                                             \
    const __half* sA = Ah + (size_t)(row0 + rr) * DMODEL + (KC) * 64 + seg * 8; \
    uint32_t dA = sb + (BUF) * QBUFB + (uint32_t)rr * 128 + sw;               \
    _Pragma("unroll")                                                         \
    for (int p = 0; p < 8; p++)                                               \
        cp_async16(dA + p * 2048, sA + (size_t)p * 16 * DMODEL);              \
    const __half* sB = Bh + (size_t)(col0 + rr) * DMODEL + (KC) * 64 + seg * 8; \
    uint32_t dB = sb + (BUF) * QBUFB + 16384 + (uint32_t)rr * 128 + sw;       \
    _Pragma("unroll")                                                         \
    for (int p = 0; p < 4; p++)                                               \
        cp_async16(dB + p * 2048, sB + (size_t)p * 16 * DMODEL);              \
} while (0)

    float acc[4][4][4];
#pragma unroll
    for (int i = 0; i < 4; i++)
#pragma unroll
        for (int j = 0; j < 4; j++)
#pragma unroll
            for (int e = 0; e < 4; e++) acc[i][j][e] = 0.0f;

    const uint32_t xa   = lane & 7;
    const int aSel      = lane >> 4;
    const int bSel      = (lane >> 3) & 1;
    const uint32_t aRow = (uint32_t)(m0w + (lane & 15)) * 128;
    const uint32_t bRow = (uint32_t)(n0w + ((lane >> 4) << 3) + (lane & 7)) * 128;

    QCOPY_CHUNK(0, 0);
    CP_COMMIT();

    for (int kc = 0; kc < 16; kc++) {
        if (kc < 15) {
            QCOPY_CHUNK(kc + 1, (kc + 1) & 1);
            CP_COMMIT();
            CP_WAIT(1);
        } else {
            CP_WAIT(0);
        }
        __syncthreads();

        const uint32_t bufb = sb + (uint32_t)(kc & 1) * QBUFB;
        const uint32_t aBase = bufb + aRow;
        const uint32_t bBase = bufb + 16384 + bRow;

#pragma unroll
        for (int ks = 0; ks < 4; ks++) {
            const uint32_t ach = (uint32_t)(((2 * ks + aSel) ^ xa) << 4);
            const uint32_t bch = (uint32_t)(((2 * ks + bSel) ^ xa) << 4);

            uint32_t ah[4][4], bh[2][4];
#pragma unroll
            for (int ma = 0; ma < 4; ma++)
                ldsm4(ah[ma], aBase + ma * 2048 + ach);
#pragma unroll
            for (int nb = 0; nb < 2; nb++)
                ldsm4(bh[nb], bBase + nb * 2048 + bch);

#pragma unroll
            for (int ma = 0; ma < 4; ma++)
#pragma unroll
                for (int na = 0; na < 4; na++) {
                    const int nb = na >> 1, sub = (na & 1) * 2;
                    mma16816(acc[ma][na], ah[ma], &bh[nb][sub]);
                }
        }
        __syncthreads();
    }
#undef QCOPY_CHUNK

    // epilogue: fp16 * oscale + bias
    const int g = lane >> 2, tg = lane & 3;
#pragma unroll
    for (int na = 0; na < 4; na++) {
        const int col = col0 + n0w + na * 8 + 2 * tg;
        const float b0 = bias[col], b1 = bias[col + 1];
#pragma unroll
        for (int ma = 0; ma < 4; ma++) {
            const int r = row0 + m0w + ma * 16 + g;
            float v0 = (acc[ma][na][0] + b0) * oscale;
            float v1 = (acc[ma][na][1] + b1) * oscale;
            float v2 = (acc[ma][na][2] + b0) * oscale;
            float v3 = (acc[ma][na][3] + b1) * oscale;
            *(__half2*)(Chi + (size_t)r * DMODEL + col) =
                __floats2half2_rn(v0, v1);
            *(__half2*)(Chi + (size_t)(r + 8) * DMODEL + col) =
                __floats2half2_rn(v2, v3);
        }
    }
}

// ---------------------------------------------------------------------------
// Output GEMM (NT): C[128,128]/CTA, 128 thr / 4 warps (2x2), 64x64 warp tile.
// (exact R11 config; fp32 + bias output)
// ---------------------------------------------------------------------------
#define BUFB     32768
#define MMA_SMEM (2 * BUFB)   // 65536

__global__ __launch_bounds__(128, 2) void out_mma(const float* __restrict__ bias,
                                                  float* __restrict__ Cf) {
    const __half* Ah = g_ch;
    const __half* Bh = g_wh[3];

    extern __shared__ char sm[];
    const uint32_t sb = smem_u32(sm);
    const int tid  = threadIdx.x;
    const int lane = tid & 31;
    const int warp = tid >> 5;            // 0..3
    const int row0 = blockIdx.y * 128;
    const int col0 = blockIdx.x * 128;
    const int m0w  = (warp >> 1) * 64;
    const int n0w  = (warp & 1) * 64;

    const int rr  = tid >> 3;             // 0..15
    const int seg = tid & 7;
    const uint32_t sw = (uint32_t)(seg ^ (rr & 7)) << 4;

    const __half* srcs[2] = {Ah, Bh};
    const int r0s[2] = {row0, col0};

#define COPY_CHUNK(KC, BUF) do {                                              \
    _Pragma("unroll")                                                         \
    for (int t = 0; t < 2; t++) {                                             \
        const __half* s_ = srcs[t] +                                          \
            (size_t)(r0s[t] + rr) * DMODEL + (KC) * 64 + seg * 8;             \
        uint32_t d_ = sb + (BUF) * BUFB + t * 16384 + (uint32_t)rr * 128 + sw;\
        _Pragma("unroll")                                                     \
        for (int p = 0; p < 8; p++)                                           \
            cp_async16(d_ + p * 2048, s_ + (size_t)p * 16 * DMODEL);          \
    }                                                                         \
} while (0)

    float acc[4][8][4];
#pragma unroll
    for (int i = 0; i < 4; i++)
#pragma unroll
        for (int j = 0; j < 8; j++)
#pragma unroll
            for (int e = 0; e < 4; e++) acc[i][j][e] = 0.0f;

    const uint32_t xa   = lane & 7;
    const int aSel      = lane >> 4;
    const int bSel      = (lane >> 3) & 1;
    const uint32_t aRow = (uint32_t)(m0w + (lane & 15)) * 128;
    const uint32_t bRow = (uint32_t)(n0w + ((lane >> 4) << 3) + (lane & 7)) * 128;

    COPY_CHUNK(0, 0);
    CP_COMMIT();

    for (int kc = 0; kc < 16; kc++) {
        if (kc < 15) {
            COPY_CHUNK(kc + 1, (kc + 1) & 1);
            CP_COMMIT();
            CP_WAIT(1);
        } else {
            CP_WAIT(0);
        }
        __syncthreads();

        const uint32_t bufb = sb + (uint32_t)(kc & 1) * BUFB;
        const uint32_t aBase = bufb + aRow;
        const uint32_t bBase = bufb + 16384 + bRow;

#pragma unroll
        for (int ks = 0; ks < 4; ks++) {
            const uint32_t ach = (uint32_t)(((2 * ks + aSel) ^ xa) << 4);
            const uint32_t bch = (uint32_t)(((2 * ks + bSel) ^ xa) << 4);

            uint32_t ah[4][4], bh[4][4];
#pragma unroll
            for (int ma = 0; ma < 4; ma++)
                ldsm4(ah[ma], aBase + ma * 2048 + ach);
#pragma unroll
            for (int nb = 0; nb < 4; nb++)
                ldsm4(bh[nb], bBase + nb * 2048 + bch);

#pragma unroll
            for (int ma = 0; ma < 4; ma++)
#pragma unroll
                for (int na = 0; na < 8; na++) {
                    const int nb = na >> 1, sub = (na & 1) * 2;
                    mma16816(acc[ma][na], ah[ma], &bh[nb][sub]);
                }
        }
        __syncthreads();
    }
#undef COPY_CHUNK

    const int g = lane >> 2, tg = lane & 3;
#pragma unroll
    for (int na = 0; na < 8; na++) {
        const int col = col0 + n0w + na * 8 + 2 * tg;
        const float b0 = bias[col], b1 = bias[col + 1];
#pragma unroll
        for (int ma = 0; ma < 4; ma++) {
            const int r = row0 + m0w + ma * 16 + g;
            *(float2*)(Cf + (size_t)r * DMODEL + col) =
                make_float2(acc[ma][na][0] + b0, acc[ma][na][1] + b1);
            *(float2*)(Cf + (size_t)(r + 8) * DMODEL + col) =
                make_float2(acc[ma][na][2] + b0, acc[ma][na][3] + b1);
        }
    }
}

// ---------------------------------------------------------------------------
// Tensor-core flash attention (exact R11 config: best measured).
// Block = 128 q rows; 128 threads / 4 warps (32 q-rows each); 2 CTAs/SM.
// smem: Q 16K | 2 stages x (K 8K | V 8K) = 48KB.
// Mask via per-128x64-tile zero flags.
// ---------------------------------------------------------------------------
#define ATT_SMEM 49152

__global__ __launch_bounds__(128, 2) void attn_mma(const float* __restrict__ Mask)
{
    extern __shared__ char sm[];
    const uint32_t sb = smem_u32(sm);
    const int tid  = threadIdx.x;
    const int lane = tid & 31;
    const int warp = tid >> 5;        // 0..3
    const int qb = blockIdx.x * 128;
    const int h  = blockIdx.y;
    const int b  = blockIdx.z;

    const int g  = lane >> 2;
    const int tg = lane & 3;
    const uint32_t xa = lane & 7;

    // ---- Q copy (128 rows x 8 segs = 1024 x 16B) ----
#pragma unroll
    for (int i = 0; i < 8; i++) {
        int s_ = tid + i * 128;
        int row = s_ >> 3, sg = s_ & 7;
        const __half* src = g_ph[0] +
            (size_t)(b * SEQ + qb + row) * DMODEL + h * HDIM + sg * 8;
        uint32_t dst = sb + row * 128 + (uint32_t)((sg ^ (row & 7)) << 4);
        cp_async16(dst, src);
    }
    CP_COMMIT();

    const __half* kvsrc[2] = {g_ph[1], g_ph[2]};
#define COPY_KV(T, SLOT) do {                                                 \
    _Pragma("unroll")                                                         \
    for (int i = 0; i < 8; i++) {                                             \
        int s_ = tid + i * 128;                                               \
        int arr = s_ >> 9, rem = s_ & 511;                                    \
        int row = rem >> 3, sg = rem & 7;                                     \
        const __half* src = kvsrc[arr] +                                      \
            (size_t)(b * SEQ + (T) * 64 + row) * DMODEL + h * HDIM + sg * 8;  \
        uint32_t dst = sb + 16384 + (SLOT) * 16384 + arr * 8192 + row * 128 + \
                       (uint32_t)((sg ^ (row & 7)) << 4);                     \
        cp_async16(dst, src);                                                 \
    }                                                                         \
} while (0)

    COPY_KV(0, 0); CP_COMMIT();
    COPY_KV(1, 1); CP_COMMIT();
    CP_WAIT(2);          // Q complete
    __syncthreads();

    // ---- Q fragments (resident): 2 m16 frags per warp ----
    uint32_t qh[2][4][4];
    {
        const int qSel = lane >> 4;
#pragma unroll
        for (int qf = 0; qf < 2; qf++) {
            const uint32_t qRow = sb +
                (uint32_t)(32 * warp + qf * 16 + (lane & 15)) * 128;
#pragma unroll
            for (int ks = 0; ks < 4; ks++) {
                const uint32_t ch = (uint32_t)(((2 * ks + qSel) ^ xa) << 4);
                ldsm4(qh[qf][ks], qRow + ch);
            }
        }
    }

    // ---- state ----
    float o[2][8][4];
#pragma unroll
    for (int qf = 0; qf < 2; qf++)
#pragma unroll
        for (int i = 0; i < 8; i++)
#pragma unroll
            for (int e = 0; e < 4; e++) o[qf][i][e] = 0.0f;
    float lp[2][2] = {{0.0f, 0.0f}, {0.0f, 0.0f}};

    const float* mrow[4];
#pragma unroll
    for (int rg = 0; rg < 4; rg++)
        mrow[rg] = Mask + ((size_t)b * SEQ + (qb + 32 * warp + 8 * rg + g)) * SEQ;
    const unsigned char* mzrow = g_mzero + (b * 16 + blockIdx.x) * 32;

    const uint32_t kRowB = (uint32_t)((((lane >> 4) << 3) + (lane & 7)) * 128);
    const int kSel = (lane >> 3) & 1;
    const uint32_t vRowB = (uint32_t)(((lane & 7) + (((lane >> 3) & 1) << 3)) * 128);
    const int vSel = lane >> 4;

    for (int t = 0; t < 32; t++) {
        if (t < 31) { CP_WAIT(1); } else { CP_WAIT(0); }
        __syncthreads();
        const uint32_t stg = sb + 16384 + (uint32_t)(t & 1) * 16384;

        // ---- S = Q K^T (both q-frags share each K fragment) ----
        float s[2][8][4];
#pragma unroll
        for (int qf = 0; qf < 2; qf++)
#pragma unroll
            for (int i = 0; i < 8; i++)
#pragma unroll
                for (int e = 0; e < 4; e++) s[qf][i][e] = 0.0f;

#pragma unroll
        for (int ks = 0; ks < 4; ks++) {
            const uint32_t kch = (uint32_t)(((2 * ks + kSel) ^ xa) << 4);
#pragma unroll
            for (int np = 0; np < 4; np++) {
                uint32_t kh[4];
                ldsm4(kh, stg + kRowB + np * 2048 + kch);
                mma16816(s[0][2 * np],     qh[0][ks], kh);
                mma16816(s[0][2 * np + 1], qh[0][ks], kh + 2);
                mma16816(s[1][2 * np],     qh[1][ks], kh);
                mma16816(s[1][2 * np + 1], qh[1][ks], kh + 2);
            }
        }

        // ---- softmax: p = ex2(s [+ mask*log2e]); accumulate l; pack P ----
        uint32_t aP[2][4][4];
        if (mzrow[t]) {
#pragma unroll
            for (int qf = 0; qf < 2; qf++) {
                __half2 accA = __floats2half2_rn(0.0f, 0.0f);
                __half2 accB = accA;
#pragma unroll
                for (int nt = 0; nt < 8; nt++) {
                    uint32_t pA = ex2h2(h2_as_u32(
                        __floats2half2_rn(s[qf][nt][0], s[qf][nt][1])));
                    uint32_t pB = ex2h2(h2_as_u32(
                        __floats2half2_rn(s[qf][nt][2], s[qf][nt][3])));
                    accA = __hadd2(accA, u32_as_h2(pA));
                    accB = __hadd2(accB, u32_as_h2(pB));
                    const int ks = nt >> 1, half = nt & 1;
                    aP[qf][ks][2 * half + 0] = pA;
                    aP[qf][ks][2 * half + 1] = pB;
                }
                float2 fa = __half22float2(accA);
                float2 fb = __half22float2(accB);
                lp[qf][0] += fa.x + fa.y;
                lp[qf][1] += fb.x + fb.y;
            }
        } else {
            const int kt0 = t * 64;
#pragma unroll
            for (int qf = 0; qf < 2; qf++) {
#pragma unroll
                for (int nt = 0; nt < 8; nt++) {
                    const int kcol = kt0 + 8 * nt + 2 * tg;
                    float2 q0 = *(const float2*)(mrow[2 * qf] + kcol);
                    float2 q1 = *(const float2*)(mrow[2 * qf + 1] + kcol);
                    float p0 = ex2f(fmaf(q0.x, LOG2E, s[qf][nt][0]));
                    float p1 = ex2f(fmaf(q0.y, LOG2E, s[qf][nt][1]));
                    float p2 = ex2f(fmaf(q1.x, LOG2E, s[qf][nt][2]));
                    float p3 = ex2f(fmaf(q1.y, LOG2E, s[qf][nt][3]));
                    lp[qf][0] += p0 + p1;
                    lp[qf][1] += p2 + p3;
                    const int ks = nt >> 1, half = nt & 1;
                    aP[qf][ks][2 * half + 0] = h2_as_u32(__floats2half2_rn(p0, p1));
                    aP[qf][ks][2 * half + 1] = h2_as_u32(__floats2half2_rn(p2, p3));
                }
            }
        }

        // ---- O += P V (both q-frags share each V fragment) ----
#pragma unroll
        for (int ks = 0; ks < 4; ks++) {
#pragma unroll
            for (int np = 0; np < 4; np++) {
                const uint32_t vch = (uint32_t)(((2 * np + vSel) ^ xa) << 4);
                uint32_t vh[4];
                ldsm4t(vh, stg + 8192 + vRowB + ks * 2048 + vch);
                mma16816(o[0][2 * np],     aP[0][ks], vh);
                mma16816(o[0][2 * np + 1], aP[0][ks], vh + 2);
                mma16816(o[1][2 * np],     aP[1][ks], vh);
                mma16816(o[1][2 * np + 1], aP[1][ks], vh + 2);
            }
        }

        __syncthreads();
        if (t + 2 < 32) { COPY_KV(t + 2, t & 1); CP_COMMIT(); }
    }

    // ---- final l reduction + epilogue (ctx fp16) ----
#pragma unroll
    for (int qf = 0; qf < 2; qf++)
#pragma unroll
        for (int r = 0; r < 2; r++) {
            lp[qf][r] += __shfl_xor_sync(0xffffffffu, lp[qf][r], 1);
            lp[qf][r] += __shfl_xor_sync(0xffffffffu, lp[qf][r], 2);
        }

#pragma unroll
    for (int qf = 0; qf < 2; qf++) {
        const float inv0 = 1.0f / lp[qf][0], inv1 = 1.0f / lp[qf][1];
        const size_t obase =
            (size_t)(b * SEQ + qb + 32 * warp + qf * 16) * DMODEL + h * HDIM;
#pragma unroll
        for (int nt = 0; nt < 8; nt++) {
            const int col = 8 * nt + 2 * tg;
            *(__half2*)(g_ch + obase + (size_t)g * DMODEL + col) =
                __floats2half2_rn(o[qf][nt][0] * inv0, o[qf][nt][1] * inv0);
            *(__half2*)(g_ch + obase + (size_t)(g + 8) * DMODEL + col) =
                __floats2half2_rn(o[qf][nt][2] * inv1, o[qf][nt][3] * inv1);
        }
    }
#undef COPY_KV
}

// ---------------------------------------------------------------------------
// Launch
// ---------------------------------------------------------------------------
extern "C" void kernel_launch(void* const* d_in, const int* in_sizes, int n_in,
                              void* d_out, int out_size)
{
    const float* query = (const float*)d_in[0];
    const float* key   = (const float*)d_in[1];
    const float* value = (const float*)d_in[2];
    const float* mask  = (const float*)d_in[3];
    const float* WQ_w  = (const float*)d_in[4];
    const float* WQ_b  = (const float*)d_in[5];
    const float* WK_w  = (const float*)d_in[6];
    const float* WK_b  = (const float*)d_in[7];
    const float* WV_w  = (const float*)d_in[8];
    const float* WV_b  = (const float*)d_in[9];
    const float* WO_w  = (const float*)d_in[10];
    const float* WO_b  = (const float*)d_in[11];
    float* out = (float*)d_out;

    cudaFuncSetAttribute(qkv_mma, cudaFuncAttributeMaxDynamicSharedMemorySize, QKV_SMEM);
    cudaFuncSetAttribute(out_mma, cudaFuncAttributeMaxDynamicSharedMemorySize, MMA_SMEM);
    cudaFuncSetAttribute(attn_mma, cudaFuncAttributeMaxDynamicSharedMemorySize, ATT_SMEM);

    // 1) convert inputs + weights to fp16; mask tile flags
    split_act<<<dim3(MTOT * DMODEL / 1024, 3), 256>>>(query, key, value);
    split_w<<<dim3(DMODEL * DMODEL / 1024, 4), 256>>>(WQ_w, WK_w, WV_w, WO_w);
    mask_flags<<<dim3(32, 16, BATCH), 256>>>(mask);

    // 2) QKV projections (tensor cores), 128x64 tiles, 3 CTAs/SM
    qkv_mma<<<dim3(DMODEL / 64, MTOT / 128, 3), 128, QKV_SMEM>>>(WQ_b, WK_b, WV_b);

    // 3) tensor-core flash attention -> ctx fp16 (2 CTAs/SM)
    attn_mma<<<dim3(SEQ / 128, NHEAD, BATCH), 128, ATT_SMEM>>>(mask);

    // 4) output projection (tensor cores), fp32 out
    out_mma<<<dim3(DMODEL / 128, MTOT / 128), 128, MMA_SMEM>>>(WO_b, out);
}